// round 13
// baseline (speedup 1.0000x reference)
#include <cuda_runtime.h>
#include <cuda_bf16.h>
#include <math.h>
#include <stdint.h>

#define BB 256
#define INF 256
#define HH 256
#define KTOT 512
#define NG 1024
#define NSTK 129
#define STACKN ((size_t)NSTK * BB * HH * 2)

// ---------------- scratch ----------------
__device__ float g_Cp0[BB * HH], g_Cp1[BB * HH];
__device__ float g_H0[BB * HH], g_C0[BB * HH];
__device__ float g_H1[BB * HH], g_C1[BB * HH];
__device__ float g_Bias0[NG], g_Bias1[NG];     // gate-interleaved combined bias
__device__ __align__(16) __nv_bfloat16 g_XH0hi[BB * KTOT], g_XH0lo[BB * KTOT];
__device__ __align__(16) __nv_bfloat16 g_XH1hi[BB * KTOT], g_XH1lo[BB * KTOT];
__device__ __align__(16) __nv_bfloat16 g_W0hi[NG * KTOT], g_W0lo[NG * KTOT];   // [n'][k], n' = h*4+gate
__device__ __align__(16) __nv_bfloat16 g_W1hi[NG * KTOT], g_W1lo[NG * KTOT];

__device__ __forceinline__ uint32_t smem_u32(const void* p) {
    uint32_t a;
    asm("{ .reg .u64 t; cvta.to.shared.u64 t, %1; cvt.u32.u64 %0, t; }" : "=r"(a) : "l"(p));
    return a;
}
__device__ __forceinline__ void cp16(uint32_t saddr, const void* gaddr) {
    asm volatile("cp.async.cg.shared.global [%0], [%1], 16;" :: "r"(saddr), "l"(gaddr));
}
#define CP_COMMIT() asm volatile("cp.async.commit_group;" ::: "memory")
#define CP_WAIT(n)  asm volatile("cp.async.wait_group %0;" :: "n"(n) : "memory")

__device__ __forceinline__ void bfsplit(float v, __nv_bfloat16& hi, __nv_bfloat16& lo) {
    hi = __float2bfloat16(v);
    lo = __float2bfloat16(v - __bfloat162float(hi));
}

__device__ __forceinline__ void hmma(float* c, uint32_t a0, uint32_t a1, uint32_t a2, uint32_t a3,
                                     uint32_t b0, uint32_t b1) {
    asm volatile(
        "mma.sync.aligned.m16n8k16.row.col.f32.bf16.bf16.f32 "
        "{%0,%1,%2,%3}, {%4,%5,%6,%7}, {%8,%9}, {%0,%1,%2,%3};"
        : "+f"(c[0]), "+f"(c[1]), "+f"(c[2]), "+f"(c[3])
        : "r"(a0), "r"(a1), "r"(a2), "r"(a3), "r"(b0), "r"(b1));
}

// ---------------- prologue: gather + weight split (gate-interleaved) + bias ----------------
#define WPREP_CTAS 128
union BF8U { __nv_bfloat16 b[8]; uint4 u; };

__global__ void __launch_bounds__(256) k_prologue(
        const float* __restrict__ x, const float* __restrict__ hs, const float* __restrict__ cs,
        const float* __restrict__ wih0, const float* __restrict__ whh0,
        const float* __restrict__ bih0, const float* __restrict__ bhh0,
        const float* __restrict__ wih1, const float* __restrict__ whh1,
        const float* __restrict__ bih1, const float* __restrict__ bhh1,
        const int* __restrict__ pos) {
    int bid = blockIdx.x;
    int t = threadIdx.x;
    if (bid < BB) {
        int b = bid, h = t;
        int s = pos[b];
        size_t idx = (((size_t)s * BB + b) * HH + h) * 2;
        float2 hv = *(const float2*)(hs + idx);
        float2 cv = *(const float2*)(cs + idx);
        __nv_bfloat16 hi, lo;
        bfsplit(x[b * INF + h], hi, lo);
        g_XH0hi[b * KTOT + h] = hi; g_XH0lo[b * KTOT + h] = lo;
        bfsplit(hv.x, hi, lo);
        g_XH0hi[b * KTOT + INF + h] = hi; g_XH0lo[b * KTOT + INF + h] = lo;
        bfsplit(hv.y, hi, lo);
        g_XH1hi[b * KTOT + INF + h] = hi; g_XH1lo[b * KTOT + INF + h] = lo;
        g_Cp0[b * HH + h] = cv.x;
        g_Cp1[b * HH + h] = cv.y;
        return;
    }
    if (bid < BB + WPREP_CTAS) {
        // weight split into bf16 hi/lo; layout [n'][k], n' = h*4+gate, k = [wih | whh]
        int tid0 = (bid - BB) * 256 + t;
        for (int g = tid0; g < 2 * NG * 64; g += WPREP_CTAS * 256) {
            int layer = g >> 16;
            int rem = g & 65535;
            int np = rem >> 6;               // n' 0..1023
            int k8 = (rem & 63) * 8;
            int hid = np >> 2, gate = np & 3;
            int orign = gate * HH + hid;
            const float* wih = layer ? wih1 : wih0;
            const float* whh = layer ? whh1 : whh0;
            const float* srcp = (k8 < INF) ? (wih + (size_t)orign * INF + k8)
                                           : (whh + (size_t)orign * INF + (k8 - INF));
            float4 a = *(const float4*)srcp;
            float4 bq = *(const float4*)(srcp + 4);
            float v[8] = {a.x, a.y, a.z, a.w, bq.x, bq.y, bq.z, bq.w};
            BF8U uhi, ulo;
#pragma unroll
            for (int j = 0; j < 8; j++) bfsplit(v[j], uhi.b[j], ulo.b[j]);
            __nv_bfloat16* dhi = layer ? g_W1hi : g_W0hi;
            __nv_bfloat16* dlo = layer ? g_W1lo : g_W0lo;
            *(uint4*)(dhi + (size_t)np * KTOT + k8) = uhi.u;
            *(uint4*)(dlo + (size_t)np * KTOT + k8) = ulo.u;
        }
        return;
    }
    // combined bias in n'-space
#pragma unroll
    for (int e = 0; e < 8; e++) {
        int idx = e * 256 + t;
        int layer = idx >> 10;
        int np = idx & 1023;
        int hid = np >> 2, gate = np & 3;
        int orign = gate * HH + hid;
        float v = (layer ? bih1 : bih0)[orign] + (layer ? bhh1 : bhh0)[orign];
        (layer ? g_Bias1 : g_Bias0)[np] = v;
    }
}

// ---------------- fused HMMA GEMM + LSTM epilogue ----------------
// gates'[256, 1024] = XH[256,512] @ W'[1024,512]^T  (n' gate-interleaved)
// 128 CTAs: tile 32(m) x 64(n'), 8 warps, warp tile 16x16.
// K chunks of 32, 4-stage cp.async pipeline. 3-term bf16 split.
#define GEMM_CTAS 128
#define APAD 40                          // bf16 row stride in smem
#define A_BYTES (32 * APAD * 2)          // 2560 per A array
#define B_BYTES (64 * APAD * 2)          // 5120 per B array
#define STAGE_BYTES (2 * A_BYTES + 2 * B_BYTES)   // 15360
#define SMEM_GEMM (4 * STAGE_BYTES)               // 61440
#define OFF_AH(p) ((p) * STAGE_BYTES)
#define OFF_AL(p) ((p) * STAGE_BYTES + A_BYTES)
#define OFF_BH(p) ((p) * STAGE_BYTES + 2 * A_BYTES)
#define OFF_BL(p) ((p) * STAGE_BYTES + 2 * A_BYTES + B_BYTES)
#define NCHUNK 16

template <int LAYER>
__global__ void __launch_bounds__(256) k_gemm(
        const float* __restrict__ hs, const float* __restrict__ cs,
        const int* __restrict__ op, const int* __restrict__ pos,
        float* __restrict__ out) {
    const int bid = blockIdx.x;
    const int t = threadIdx.x;

    extern __shared__ char smem[];
    const uint32_t sb = smem_u32(smem);

    const __nv_bfloat16* __restrict__ Ahi = LAYER ? g_XH1hi : g_XH0hi;
    const __nv_bfloat16* __restrict__ Alo = LAYER ? g_XH1lo : g_XH0lo;
    const __nv_bfloat16* __restrict__ Bhi = LAYER ? g_W1hi : g_W0hi;
    const __nv_bfloat16* __restrict__ Blo = LAYER ? g_W1lo : g_W0lo;

    const int m0 = (bid & 7) * 32;      // 8 m tiles
    const int n0 = (bid >> 3) * 64;     // 16 n' tiles
    const int wid = t >> 5, lane = t & 31;
    const int wm = (wid & 1) * 16;      // warp m offset (0/16)
    const int wn = (wid >> 1) * 16;     // warp n offset (0..48)
    const int lr = lane >> 2;           // 0..7
    const int lc = (lane & 3) * 2;      // 0,2,4,6

    const int arow = (t >> 2) & 31, aj = t & 3;
    const int brow = t >> 2, bj = t & 3;

    float acc[2][4];
#pragma unroll
    for (int j = 0; j < 2; j++)
#pragma unroll
        for (int q = 0; q < 4; q++) acc[j][q] = 0.f;

    auto load_chunk = [&](int c, int p) {
        int kc = c * 32;
        const __nv_bfloat16* Asrc = (t < 128) ? Ahi : Alo;
        uint32_t aoff = (t < 128) ? OFF_AH(p) : OFF_AL(p);
        cp16(sb + aoff + arow * (APAD * 2) + aj * 16,
             Asrc + (size_t)(m0 + arow) * KTOT + kc + aj * 8);
        cp16(sb + OFF_BH(p) + brow * (APAD * 2) + bj * 16,
             Bhi + (size_t)(n0 + brow) * KTOT + kc + bj * 8);
        cp16(sb + OFF_BL(p) + brow * (APAD * 2) + bj * 16,
             Blo + (size_t)(n0 + brow) * KTOT + kc + bj * 8);
    };

    load_chunk(0, 0); CP_COMMIT();
    load_chunk(1, 1); CP_COMMIT();
    load_chunk(2, 2); CP_COMMIT();

#pragma unroll 1
    for (int c = 0; c < NCHUNK; c++) {
        int p = c & 3;
        if (c < NCHUNK - 2)      { CP_WAIT(2); }
        else if (c == NCHUNK - 2){ CP_WAIT(1); }
        else                     { CP_WAIT(0); }
        __syncthreads();
        if (c + 3 < NCHUNK) { load_chunk(c + 3, (c + 3) & 3); CP_COMMIT(); }

        const __nv_bfloat16* ah = (const __nv_bfloat16*)(smem + OFF_AH(p));
        const __nv_bfloat16* al = (const __nv_bfloat16*)(smem + OFF_AL(p));
        const __nv_bfloat16* bh = (const __nv_bfloat16*)(smem + OFF_BH(p));
        const __nv_bfloat16* bl = (const __nv_bfloat16*)(smem + OFF_BL(p));

#pragma unroll
        for (int k0 = 0; k0 < 32; k0 += 16) {
            const int r = wm + lr;
            const int cc = k0 + lc;
            uint32_t AH4[4], AL4[4], BH[2][2], BL[2][2];
            AH4[0] = *(const uint32_t*)(ah + r * APAD + cc);
            AH4[1] = *(const uint32_t*)(ah + (r + 8) * APAD + cc);
            AH4[2] = *(const uint32_t*)(ah + r * APAD + cc + 8);
            AH4[3] = *(const uint32_t*)(ah + (r + 8) * APAD + cc + 8);
            AL4[0] = *(const uint32_t*)(al + r * APAD + cc);
            AL4[1] = *(const uint32_t*)(al + (r + 8) * APAD + cc);
            AL4[2] = *(const uint32_t*)(al + r * APAD + cc + 8);
            AL4[3] = *(const uint32_t*)(al + (r + 8) * APAD + cc + 8);
#pragma unroll
            for (int nt = 0; nt < 2; nt++) {
                int n = wn + nt * 8 + lr;
                BH[nt][0] = *(const uint32_t*)(bh + n * APAD + cc);
                BH[nt][1] = *(const uint32_t*)(bh + n * APAD + cc + 8);
                BL[nt][0] = *(const uint32_t*)(bl + n * APAD + cc);
                BL[nt][1] = *(const uint32_t*)(bl + n * APAD + cc + 8);
            }
#pragma unroll
            for (int nt = 0; nt < 2; nt++) {
                hmma(acc[nt], AH4[0], AH4[1], AH4[2], AH4[3], BH[nt][0], BH[nt][1]);
                hmma(acc[nt], AH4[0], AH4[1], AH4[2], AH4[3], BL[nt][0], BL[nt][1]);
                hmma(acc[nt], AL4[0], AL4[1], AL4[2], AL4[3], BH[nt][0], BH[nt][1]);
            }
        }
        __syncthreads();
    }

    // ---- fused LSTM epilogue (no stack writes here; scatter kernel owns those) ----
    float* Gs = (float*)smem;   // 32 x 68 fp32 gates (pre-bias)
    __syncthreads();
#pragma unroll
    for (int nt = 0; nt < 2; nt++) {
        int r = wm + lr;
        int n = wn + nt * 8 + lc;
        *(float2*)(Gs + r * 68 + n)       = make_float2(acc[nt][0], acc[nt][1]);
        *(float2*)(Gs + (r + 8) * 68 + n) = make_float2(acc[nt][2], acc[nt][3]);
    }
    __syncthreads();

    const float* __restrict__ Bias = LAYER ? g_Bias1 : g_Bias0;
    const float* __restrict__ Cp   = LAYER ? g_Cp1 : g_Cp0;
#pragma unroll
    for (int j = 0; j < 2; j++) {
        int p2 = t + 256 * j;           // 0..511 -> (mb, hh)
        int mb = p2 >> 4, hh = p2 & 15;
        int b = m0 + mb, h = (n0 >> 2) + hh;
        float4 g4 = *(const float4*)(Gs + mb * 68 + hh * 4);
        float4 bi4 = *(const float4*)(Bias + n0 + hh * 4);
        float gi = g4.x + bi4.x, gf = g4.y + bi4.y, gg = g4.z + bi4.z, go = g4.w + bi4.w;
        float si = 1.0f / (1.0f + expf(-gi));
        float sf = 1.0f / (1.0f + expf(-gf));
        float so = 1.0f / (1.0f + expf(-go));
        float c2 = sf * Cp[b * HH + h] + si * tanhf(gg);
        float h2 = so * tanhf(c2);

        if (LAYER == 0) {
            g_H0[b * HH + h] = h2;
            g_C0[b * HH + h] = c2;
            __nv_bfloat16 hi_, lo_;
            bfsplit(h2, hi_, lo_);
            g_XH1hi[b * KTOT + h] = hi_;
            g_XH1lo[b * KTOT + h] = lo_;
        } else {
            g_H1[b * HH + h] = h2;
            g_C1[b * HH + h] = c2;
            if (h == HH - 1) {
                // h_out/c_out live in out[0 .. 1024), disjoint from the memcpy regions
                int pp = pos[b];
                float h0 = g_H0[b * HH + h];
                float c0 = g_C0[b * HH + h];
                int o = op[b];
                float2 hv, cv;
                if (o == 1) { hv = make_float2(h0, h2); cv = make_float2(c0, c2); }
                else {
                    size_t gi2 = (((size_t)(pp + o) * BB + b) * HH + (HH - 1)) * 2;
                    hv = *(const float2*)(hs + gi2);
                    cv = *(const float2*)(cs + gi2);
                }
                *(float2*)(out + b * 2) = hv;            // h_out (1,B,L)
                *(float2*)(out + BB * 2 + b * 2) = cv;   // c_out (1,B,L)
            }
        }
    }
}

// ---------------- scatter: overwrite pos+1 rows after the bulk memcpy ----------------
__global__ void k_scatter(float* __restrict__ hs_out, float* __restrict__ cs_out,
                          const int* __restrict__ pos) {
    int b = blockIdx.x;
    int h = threadIdx.x;
    int p = pos[b];
    size_t base = (((size_t)(p + 1) * BB + b) * HH + h) * 2;
    *(float2*)(hs_out + base) = make_float2(g_H0[b * HH + h], g_H1[b * HH + h]);
    *(float2*)(cs_out + base) = make_float2(g_C0[b * HH + h], g_C1[b * HH + h]);
}

// ---------------- launch ----------------
extern "C" void kernel_launch(void* const* d_in, const int* in_sizes, int n_in,
                              void* d_out, int out_size) {
    const float* x    = (const float*)d_in[0];
    const float* hs   = (const float*)d_in[1];
    const float* cs   = (const float*)d_in[2];
    const float* wih0 = (const float*)d_in[3];
    const float* whh0 = (const float*)d_in[4];
    const float* bih0 = (const float*)d_in[5];
    const float* bhh0 = (const float*)d_in[6];
    const float* wih1 = (const float*)d_in[7];
    const float* whh1 = (const float*)d_in[8];
    const float* bih1 = (const float*)d_in[9];
    const float* bhh1 = (const float*)d_in[10];
    const int*   op   = (const int*)d_in[11];
    const int*   pos  = (const int*)d_in[12];
    float* out = (float*)d_out;

    float* hs_out = out + 2 * BB * 2;
    float* cs_out = hs_out + STACKN;

    static cudaStream_t s2 = nullptr, s3 = nullptr;
    static cudaEvent_t evFork = nullptr, evC2 = nullptr, evC3 = nullptr;
    if (!s2) {
        cudaStreamCreate(&s2);
        cudaStreamCreate(&s3);
        cudaEventCreateWithFlags(&evFork, cudaEventDisableTiming);
        cudaEventCreateWithFlags(&evC2, cudaEventDisableTiming);
        cudaEventCreateWithFlags(&evC3, cudaEventDisableTiming);
        cudaFuncSetAttribute(k_gemm<0>, cudaFuncAttributeMaxDynamicSharedMemorySize, SMEM_GEMM);
        cudaFuncSetAttribute(k_gemm<1>, cudaFuncAttributeMaxDynamicSharedMemorySize, SMEM_GEMM);
    }

    // fork: bulk stack copies via memcpy nodes (copy-engine path, no SM contention)
    cudaEventRecord(evFork, 0);
    cudaStreamWaitEvent(s2, evFork, 0);
    cudaStreamWaitEvent(s3, evFork, 0);
    cudaMemcpyAsync(hs_out, hs, STACKN * sizeof(float), cudaMemcpyDeviceToDevice, s2);
    cudaMemcpyAsync(cs_out, cs, STACKN * sizeof(float), cudaMemcpyDeviceToDevice, s3);
    cudaEventRecord(evC2, s2);
    cudaEventRecord(evC3, s3);

    // compute chain on the main stream, concurrent with the copies
    k_prologue<<<BB + WPREP_CTAS + 1, 256>>>(
        x, hs, cs, wih0, whh0, bih0, bhh0, wih1, whh1, bih1, bhh1, pos);
    k_gemm<0><<<GEMM_CTAS, 256, SMEM_GEMM>>>(hs, cs, op, pos, out);
    k_gemm<1><<<GEMM_CTAS, 256, SMEM_GEMM>>>(hs, cs, op, pos, out);

    // join: scatter must run after both memcpys land
    cudaStreamWaitEvent(0, evC2, 0);
    cudaStreamWaitEvent(0, evC3, 0);
    k_scatter<<<BB, HH>>>(hs_out, cs_out, pos);
}

// round 14
// speedup vs baseline: 1.0469x; 1.0469x over previous
#include <cuda_runtime.h>
#include <cuda_bf16.h>
#include <math.h>
#include <stdint.h>

#define BB 256
#define INF 256
#define HH 256
#define KTOT 512
#define NG 1024
#define NSTK 129
#define STACKN ((size_t)NSTK * BB * HH * 2)
#define ROWS_PER_STACK ((long)NSTK * BB)       // 33024
#define ROWS_TOTAL (2 * ROWS_PER_STACK)        // 66048
#define PAIRS_TOTAL (ROWS_TOTAL / 2)           // 33024

// ---------------- scratch ----------------
__device__ float g_Cp0[BB * HH], g_Cp1[BB * HH];
__device__ float g_H0[BB * HH], g_C0[BB * HH];
__device__ float g_Bias0[NG], g_Bias1[NG];     // gate-interleaved combined bias
__device__ __align__(16) __nv_bfloat16 g_XH0hi[BB * KTOT], g_XH0lo[BB * KTOT];
__device__ __align__(16) __nv_bfloat16 g_XH1hi[BB * KTOT], g_XH1lo[BB * KTOT];
__device__ __align__(16) __nv_bfloat16 g_W0hi[NG * KTOT], g_W0lo[NG * KTOT];   // [n'][k], n' = h*4+gate
__device__ __align__(16) __nv_bfloat16 g_W1hi[NG * KTOT], g_W1lo[NG * KTOT];

__device__ __forceinline__ uint32_t smem_u32(const void* p) {
    uint32_t a;
    asm("{ .reg .u64 t; cvta.to.shared.u64 t, %1; cvt.u32.u64 %0, t; }" : "=r"(a) : "l"(p));
    return a;
}
__device__ __forceinline__ void cp16(uint32_t saddr, const void* gaddr) {
    asm volatile("cp.async.cg.shared.global [%0], [%1], 16;" :: "r"(saddr), "l"(gaddr));
}
#define CP_COMMIT() asm volatile("cp.async.commit_group;" ::: "memory")
#define CP_WAIT(n)  asm volatile("cp.async.wait_group %0;" :: "n"(n) : "memory")

__device__ __forceinline__ void bfsplit(float v, __nv_bfloat16& hi, __nv_bfloat16& lo) {
    hi = __float2bfloat16(v);
    lo = __float2bfloat16(v - __bfloat162float(hi));
}

__device__ __forceinline__ void hmma(float* c, uint32_t a0, uint32_t a1, uint32_t a2, uint32_t a3,
                                     uint32_t b0, uint32_t b1) {
    asm volatile(
        "mma.sync.aligned.m16n8k16.row.col.f32.bf16.bf16.f32 "
        "{%0,%1,%2,%3}, {%4,%5,%6,%7}, {%8,%9}, {%0,%1,%2,%3};"
        : "+f"(c[0]), "+f"(c[1]), "+f"(c[2]), "+f"(c[3])
        : "r"(a0), "r"(a1), "r"(a2), "r"(a3), "r"(b0), "r"(b1));
}

// ---------------- full-stack copy: warp handles 2 rows/iter (8 LDG.128 in flight) ----------------
// 888 CTAs = 6/SM -> leaves 512 threads/SM for one gemm CTA to co-schedule.
// Skips rows s == pos[b]+1 (gemm1 epilogue owns them) -> no ordering dependency.
#define COPY_CTAS 888
__global__ void __launch_bounds__(256) k_copy(
        const float* __restrict__ hs, const float* __restrict__ cs,
        float* __restrict__ hs_out, float* __restrict__ cs_out,
        const int* __restrict__ pos) {
    int gwarp = blockIdx.x * 8 + (threadIdx.x >> 5);
    int lane = threadIdx.x & 31;
    const int nwarps = COPY_CTAS * 8;
    for (long pr = gwarp; pr < PAIRS_TOTAL; pr += nwarps) {
        long rs = pr * 2;                 // first row of the pair
        const float* src;
        float* dst;
        if (rs < ROWS_PER_STACK) { src = hs; dst = hs_out; }
        else { rs -= ROWS_PER_STACK; src = cs; dst = cs_out; }
        int s = (int)(rs >> 8);
        int b0 = (int)(rs & 255);         // even; pair is (b0, b0+1), same s
        bool w0 = (s != pos[b0] + 1);
        bool w1 = (s != pos[b0 + 1] + 1);
        const float4* s4 = (const float4*)(src + rs * 512);
        float4* d4 = (float4*)(dst + rs * 512);
        float4 v0 = __ldcs(s4 + lane);
        float4 v1 = __ldcs(s4 + lane + 32);
        float4 v2 = __ldcs(s4 + lane + 64);
        float4 v3 = __ldcs(s4 + lane + 96);
        float4 u0 = __ldcs(s4 + lane + 128);
        float4 u1 = __ldcs(s4 + lane + 160);
        float4 u2 = __ldcs(s4 + lane + 192);
        float4 u3 = __ldcs(s4 + lane + 224);
        if (w0) {
            __stcs(d4 + lane, v0);
            __stcs(d4 + lane + 32, v1);
            __stcs(d4 + lane + 64, v2);
            __stcs(d4 + lane + 96, v3);
        }
        if (w1) {
            __stcs(d4 + lane + 128, u0);
            __stcs(d4 + lane + 160, u1);
            __stcs(d4 + lane + 192, u2);
            __stcs(d4 + lane + 224, u3);
        }
    }
}

// ---------------- weight prep (s2, runs at t=0 on free machine) ----------------
#define WPREP_CTAS 256
union BF8U { __nv_bfloat16 b[8]; uint4 u; };

__global__ void __launch_bounds__(256) k_wprep(
        const float* __restrict__ wih0, const float* __restrict__ whh0,
        const float* __restrict__ bih0, const float* __restrict__ bhh0,
        const float* __restrict__ wih1, const float* __restrict__ whh1,
        const float* __restrict__ bih1, const float* __restrict__ bhh1) {
    int bid = blockIdx.x;
    int t = threadIdx.x;
    if (bid < WPREP_CTAS) {
        int tid0 = bid * 256 + t;
        for (int g = tid0; g < 2 * NG * 64; g += WPREP_CTAS * 256) {
            int layer = g >> 16;
            int rem = g & 65535;
            int np = rem >> 6;               // n' 0..1023
            int k8 = (rem & 63) * 8;
            int hid = np >> 2, gate = np & 3;
            int orign = gate * HH + hid;
            const float* wih = layer ? wih1 : wih0;
            const float* whh = layer ? whh1 : whh0;
            const float* srcp = (k8 < INF) ? (wih + (size_t)orign * INF + k8)
                                           : (whh + (size_t)orign * INF + (k8 - INF));
            float4 a = *(const float4*)srcp;
            float4 bq = *(const float4*)(srcp + 4);
            float v[8] = {a.x, a.y, a.z, a.w, bq.x, bq.y, bq.z, bq.w};
            BF8U uhi, ulo;
#pragma unroll
            for (int j = 0; j < 8; j++) bfsplit(v[j], uhi.b[j], ulo.b[j]);
            __nv_bfloat16* dhi = layer ? g_W1hi : g_W0hi;
            __nv_bfloat16* dlo = layer ? g_W1lo : g_W0lo;
            *(uint4*)(dhi + (size_t)np * KTOT + k8) = uhi.u;
            *(uint4*)(dlo + (size_t)np * KTOT + k8) = ulo.u;
        }
        return;
    }
    // combined bias in n'-space
#pragma unroll
    for (int e = 0; e < 8; e++) {
        int idx = e * 256 + t;
        int layer = idx >> 10;
        int np = idx & 1023;
        int hid = np >> 2, gate = np & 3;
        int orign = gate * HH + hid;
        float v = (layer ? bih1 : bih0)[orign] + (layer ? bhh1 : bhh0)[orign];
        (layer ? g_Bias1 : g_Bias0)[np] = v;
    }
}

// ---------------- gather: densify prev state, build XH0 hi/lo (main stream) ----------------
__global__ void k_gather(const float* __restrict__ x,
                         const float* __restrict__ hs,
                         const float* __restrict__ cs,
                         const int* __restrict__ pos) {
    int b = blockIdx.x;
    int h = threadIdx.x;
    int s = pos[b];
    size_t idx = (((size_t)s * BB + b) * HH + h) * 2;
    float2 hv = *(const float2*)(hs + idx);
    float2 cv = *(const float2*)(cs + idx);
    __nv_bfloat16 hi, lo;
    bfsplit(x[b * INF + h], hi, lo);
    g_XH0hi[b * KTOT + h] = hi; g_XH0lo[b * KTOT + h] = lo;
    bfsplit(hv.x, hi, lo);
    g_XH0hi[b * KTOT + INF + h] = hi; g_XH0lo[b * KTOT + INF + h] = lo;
    bfsplit(hv.y, hi, lo);
    g_XH1hi[b * KTOT + INF + h] = hi; g_XH1lo[b * KTOT + INF + h] = lo;
    g_Cp0[b * HH + h] = cv.x;
    g_Cp1[b * HH + h] = cv.y;
}

// ---------------- fused HMMA GEMM + LSTM epilogue ----------------
// gates'[256, 1024] = XH[256,512] @ W'[1024,512]^T  (n' gate-interleaved)
// 128 CTAs: tile 32(m) x 64(n'), 16 warps (512 thr), warp tile 16x8.
// K chunks of 32, 4-stage cp.async pipeline. 3-term bf16 split.
#define GEMM_CTAS 128
#define GEMM_THREADS 512
#define APAD 40                          // bf16 row stride in smem
#define A_BYTES (32 * APAD * 2)          // 2560 per A array
#define B_BYTES (64 * APAD * 2)          // 5120 per B array
#define STAGE_BYTES (2 * A_BYTES + 2 * B_BYTES)   // 15360
#define SMEM_GEMM (4 * STAGE_BYTES)               // 61440
#define OFF_AH(p) ((p) * STAGE_BYTES)
#define OFF_AL(p) ((p) * STAGE_BYTES + A_BYTES)
#define OFF_BH(p) ((p) * STAGE_BYTES + 2 * A_BYTES)
#define OFF_BL(p) ((p) * STAGE_BYTES + 2 * A_BYTES + B_BYTES)
#define NCHUNK 16

template <int LAYER>
__global__ void __launch_bounds__(GEMM_THREADS) k_gemm(
        const float* __restrict__ hs, const float* __restrict__ cs,
        float* __restrict__ hs_out, float* __restrict__ cs_out,
        const int* __restrict__ op, const int* __restrict__ pos,
        float* __restrict__ out) {
    const int bid = blockIdx.x;
    const int t = threadIdx.x;

    extern __shared__ char smem[];
    const uint32_t sb = smem_u32(smem);

    const __nv_bfloat16* __restrict__ Ahi = LAYER ? g_XH1hi : g_XH0hi;
    const __nv_bfloat16* __restrict__ Alo = LAYER ? g_XH1lo : g_XH0lo;
    const __nv_bfloat16* __restrict__ Bhi = LAYER ? g_W1hi : g_W0hi;
    const __nv_bfloat16* __restrict__ Blo = LAYER ? g_W1lo : g_W0lo;

    const int m0 = (bid & 7) * 32;      // 8 m tiles
    const int n0 = (bid >> 3) * 64;     // 16 n' tiles
    const int wid = t >> 5, lane = t & 31;
    const int wm = (wid & 1) * 16;      // warp m offset (0/16)
    const int wn = (wid >> 1) * 8;      // warp n offset (0..56), 8 warps in n
    const int lr = lane >> 2;           // 0..7
    const int lc = (lane & 3) * 2;      // 0,2,4,6

    // cp.async per-thread assignments (768 cp16 per chunk, 512 threads):
    //  t 0-127   : AH item t        + BL item t
    //  t 128-255 : AL item (t-128)  + BL item t
    //  t 256-511 : BH item (t-256)
    const int aitem = t & 127;
    const int arow = aitem >> 2, aj = aitem & 3;         // A: 32 rows x 4
    const int bitem = (t < 256) ? t : (t - 256);
    const int brow = bitem >> 2, bj = bitem & 3;         // B: 64 rows x 4

    float acc[4];
    acc[0] = acc[1] = acc[2] = acc[3] = 0.f;

    auto load_chunk = [&](int c, int p) {
        int kc = c * 32;
        if (t < 256) {
            const __nv_bfloat16* Asrc = (t < 128) ? Ahi : Alo;
            uint32_t aoff = (t < 128) ? OFF_AH(p) : OFF_AL(p);
            cp16(sb + aoff + arow * (APAD * 2) + aj * 16,
                 Asrc + (size_t)(m0 + arow) * KTOT + kc + aj * 8);
            cp16(sb + OFF_BL(p) + brow * (APAD * 2) + bj * 16,
                 Blo + (size_t)(n0 + brow) * KTOT + kc + bj * 8);
        } else {
            cp16(sb + OFF_BH(p) + brow * (APAD * 2) + bj * 16,
                 Bhi + (size_t)(n0 + brow) * KTOT + kc + bj * 8);
        }
    };

    load_chunk(0, 0); CP_COMMIT();
    load_chunk(1, 1); CP_COMMIT();
    load_chunk(2, 2); CP_COMMIT();

#pragma unroll 1
    for (int c = 0; c < NCHUNK; c++) {
        int p = c & 3;
        if (c < NCHUNK - 2)      { CP_WAIT(2); }
        else if (c == NCHUNK - 2){ CP_WAIT(1); }
        else                     { CP_WAIT(0); }
        __syncthreads();
        if (c + 3 < NCHUNK) { load_chunk(c + 3, (c + 3) & 3); CP_COMMIT(); }

        const __nv_bfloat16* ah = (const __nv_bfloat16*)(smem + OFF_AH(p));
        const __nv_bfloat16* al = (const __nv_bfloat16*)(smem + OFF_AL(p));
        const __nv_bfloat16* bh = (const __nv_bfloat16*)(smem + OFF_BH(p));
        const __nv_bfloat16* bl = (const __nv_bfloat16*)(smem + OFF_BL(p));

#pragma unroll
        for (int k0 = 0; k0 < 32; k0 += 16) {
            const int r = wm + lr;
            const int n = wn + lr;
            const int cc = k0 + lc;
            uint32_t AH4[4], AL4[4], BH2[2], BL2[2];
            AH4[0] = *(const uint32_t*)(ah + r * APAD + cc);
            AH4[1] = *(const uint32_t*)(ah + (r + 8) * APAD + cc);
            AH4[2] = *(const uint32_t*)(ah + r * APAD + cc + 8);
            AH4[3] = *(const uint32_t*)(ah + (r + 8) * APAD + cc + 8);
            AL4[0] = *(const uint32_t*)(al + r * APAD + cc);
            AL4[1] = *(const uint32_t*)(al + (r + 8) * APAD + cc);
            AL4[2] = *(const uint32_t*)(al + r * APAD + cc + 8);
            AL4[3] = *(const uint32_t*)(al + (r + 8) * APAD + cc + 8);
            BH2[0] = *(const uint32_t*)(bh + n * APAD + cc);
            BH2[1] = *(const uint32_t*)(bh + n * APAD + cc + 8);
            BL2[0] = *(const uint32_t*)(bl + n * APAD + cc);
            BL2[1] = *(const uint32_t*)(bl + n * APAD + cc + 8);
            hmma(acc, AH4[0], AH4[1], AH4[2], AH4[3], BH2[0], BH2[1]);
            hmma(acc, AH4[0], AH4[1], AH4[2], AH4[3], BL2[0], BL2[1]);
            hmma(acc, AL4[0], AL4[1], AL4[2], AL4[3], BH2[0], BH2[1]);
        }
        __syncthreads();
    }

    // ---- fused LSTM epilogue ----
    float* Gs = (float*)smem;   // 32 x 68 fp32 gates (pre-bias), reuses stage smem
    __syncthreads();
    {
        int r = wm + lr;
        int n = wn + lc;
        *(float2*)(Gs + r * 68 + n)       = make_float2(acc[0], acc[1]);
        *(float2*)(Gs + (r + 8) * 68 + n) = make_float2(acc[2], acc[3]);
    }
    __syncthreads();

    const float* __restrict__ Bias = LAYER ? g_Bias1 : g_Bias0;
    const float* __restrict__ Cp   = LAYER ? g_Cp1 : g_Cp0;
    {
        int p2 = t;                     // 0..511 -> (mb, hh), 32 x 16
        int mb = p2 >> 4, hh = p2 & 15;
        int b = m0 + mb, h = (n0 >> 2) + hh;
        float4 g4 = *(const float4*)(Gs + mb * 68 + hh * 4);
        float4 bi4 = *(const float4*)(Bias + n0 + hh * 4);
        float gi = g4.x + bi4.x, gf = g4.y + bi4.y, gg = g4.z + bi4.z, go = g4.w + bi4.w;
        float si = 1.0f / (1.0f + expf(-gi));
        float sf = 1.0f / (1.0f + expf(-gf));
        float so = 1.0f / (1.0f + expf(-go));
        float c2 = sf * Cp[b * HH + h] + si * tanhf(gg);
        float h2 = so * tanhf(c2);

        if (LAYER == 0) {
            g_H0[b * HH + h] = h2;
            g_C0[b * HH + h] = c2;
            __nv_bfloat16 hi_, lo_;
            bfsplit(h2, hi_, lo_);
            g_XH1hi[b * KTOT + h] = hi_;
            g_XH1lo[b * KTOT + h] = lo_;
        } else {
            int pp = pos[b];
            float h0 = g_H0[b * HH + h];
            float c0 = g_C0[b * HH + h];
            size_t base = (((size_t)(pp + 1) * BB + b) * HH + h) * 2;
            *(float2*)(hs_out + base) = make_float2(h0, h2);
            *(float2*)(cs_out + base) = make_float2(c0, c2);
            if (h == HH - 1) {
                int o = op[b];
                float2 hv, cv;
                if (o == 1) { hv = make_float2(h0, h2); cv = make_float2(c0, c2); }
                else {
                    size_t gi2 = (((size_t)(pp + o) * BB + b) * HH + (HH - 1)) * 2;
                    hv = *(const float2*)(hs + gi2);
                    cv = *(const float2*)(cs + gi2);
                }
                *(float2*)(out + b * 2) = hv;            // h_out (1,B,L)
                *(float2*)(out + BB * 2 + b * 2) = cv;   // c_out (1,B,L)
            }
        }
    }
}

// ---------------- launch ----------------
extern "C" void kernel_launch(void* const* d_in, const int* in_sizes, int n_in,
                              void* d_out, int out_size) {
    const float* x    = (const float*)d_in[0];
    const float* hs   = (const float*)d_in[1];
    const float* cs   = (const float*)d_in[2];
    const float* wih0 = (const float*)d_in[3];
    const float* whh0 = (const float*)d_in[4];
    const float* bih0 = (const float*)d_in[5];
    const float* bhh0 = (const float*)d_in[6];
    const float* wih1 = (const float*)d_in[7];
    const float* whh1 = (const float*)d_in[8];
    const float* bih1 = (const float*)d_in[9];
    const float* bhh1 = (const float*)d_in[10];
    const int*   op   = (const int*)d_in[11];
    const int*   pos  = (const int*)d_in[12];
    float* out = (float*)d_out;

    float* hs_out = out + 2 * BB * 2;
    float* cs_out = hs_out + STACKN;

    static cudaStream_t s2 = nullptr;
    static cudaEvent_t evFork = nullptr, evW = nullptr, evJoin = nullptr;
    if (!s2) {
        cudaStreamCreate(&s2);
        cudaEventCreateWithFlags(&evFork, cudaEventDisableTiming);
        cudaEventCreateWithFlags(&evW, cudaEventDisableTiming);
        cudaEventCreateWithFlags(&evJoin, cudaEventDisableTiming);
        cudaFuncSetAttribute(k_gemm<0>, cudaFuncAttributeMaxDynamicSharedMemorySize, SMEM_GEMM);
        cudaFuncSetAttribute(k_gemm<1>, cudaFuncAttributeMaxDynamicSharedMemorySize, SMEM_GEMM);
    }

    // fork: s2 runs weight prep first (machine free), then the bulk copy (6 CTAs/SM)
    cudaEventRecord(evFork, 0);
    cudaStreamWaitEvent(s2, evFork, 0);
    k_wprep<<<WPREP_CTAS + 1, 256, 0, s2>>>(wih0, whh0, bih0, bhh0, wih1, whh1, bih1, bhh1);
    cudaEventRecord(evW, s2);
    k_copy<<<COPY_CTAS, 256, 0, s2>>>(hs, cs, hs_out, cs_out, pos);
    cudaEventRecord(evJoin, s2);

    // main stream: gather concurrent with wprep; gemms co-schedule into free SM slots
    k_gather<<<BB, HH>>>(x, hs, cs, pos);
    cudaStreamWaitEvent(0, evW, 0);
    k_gemm<0><<<GEMM_CTAS, GEMM_THREADS, SMEM_GEMM>>>(hs, cs, hs_out, cs_out, op, pos, out);
    k_gemm<1><<<GEMM_CTAS, GEMM_THREADS, SMEM_GEMM>>>(hs, cs, hs_out, cs_out, op, pos, out);

    // join
    cudaStreamWaitEvent(0, evJoin, 0);
}

// round 15
// speedup vs baseline: 1.2599x; 1.2035x over previous
#include <cuda_runtime.h>
#include <cuda_bf16.h>
#include <math.h>
#include <stdint.h>

#define BB 256
#define INF 256
#define HH 256
#define KTOT 512
#define NG 1024
#define NSTK 129
#define STACKN ((size_t)NSTK * BB * HH * 2)
#define ROWS_PER_STACK ((long)NSTK * BB)       // 33024
#define ROWS_TOTAL (2 * ROWS_PER_STACK)        // 66048

// ---------------- scratch ----------------
__device__ float g_Cp0[BB * HH], g_Cp1[BB * HH];
__device__ float g_H0[BB * HH], g_C0[BB * HH];
__device__ float g_Bias0[NG], g_Bias1[NG];     // gate-interleaved combined bias
__device__ __align__(16) __nv_bfloat16 g_XH0hi[BB * KTOT], g_XH0lo[BB * KTOT];
__device__ __align__(16) __nv_bfloat16 g_XH1hi[BB * KTOT], g_XH1lo[BB * KTOT];
__device__ __align__(16) __nv_bfloat16 g_W0hi[NG * KTOT], g_W0lo[NG * KTOT];   // [n'][k], n' = h*4+gate
__device__ __align__(16) __nv_bfloat16 g_W1hi[NG * KTOT], g_W1lo[NG * KTOT];

__device__ __forceinline__ uint32_t smem_u32(const void* p) {
    uint32_t a;
    asm("{ .reg .u64 t; cvta.to.shared.u64 t, %1; cvt.u32.u64 %0, t; }" : "=r"(a) : "l"(p));
    return a;
}
__device__ __forceinline__ void cp16(uint32_t saddr, const void* gaddr) {
    asm volatile("cp.async.cg.shared.global [%0], [%1], 16;" :: "r"(saddr), "l"(gaddr));
}
#define CP_COMMIT() asm volatile("cp.async.commit_group;" ::: "memory")
#define CP_WAIT(n)  asm volatile("cp.async.wait_group %0;" :: "n"(n) : "memory")

__device__ __forceinline__ void bfsplit(float v, __nv_bfloat16& hi, __nv_bfloat16& lo) {
    hi = __float2bfloat16(v);
    lo = __float2bfloat16(v - __bfloat162float(hi));
}

__device__ __forceinline__ void hmma(float* c, uint32_t a0, uint32_t a1, uint32_t a2, uint32_t a3,
                                     uint32_t b0, uint32_t b1) {
    asm volatile(
        "mma.sync.aligned.m16n8k16.row.col.f32.bf16.bf16.f32 "
        "{%0,%1,%2,%3}, {%4,%5,%6,%7}, {%8,%9}, {%0,%1,%2,%3};"
        : "+f"(c[0]), "+f"(c[1]), "+f"(c[2]), "+f"(c[3])
        : "r"(a0), "r"(a1), "r"(a2), "r"(a3), "r"(b0), "r"(b1));
}

// ---------------- full-stack copy (R7-proven 592-CTA config; forked stream) ----------------
// Skips rows s == pos[b]+1 (gemm1 epilogue owns them) -> no ordering dependency.
#define COPY_CTAS 592
__global__ void __launch_bounds__(256) k_copy(
        const float* __restrict__ hs, const float* __restrict__ cs,
        float* __restrict__ hs_out, float* __restrict__ cs_out,
        const int* __restrict__ pos) {
    int gwarp = blockIdx.x * 8 + (threadIdx.x >> 5);
    int lane = threadIdx.x & 31;
    const int nwarps = COPY_CTAS * 8;
    for (long r = gwarp; r < ROWS_TOTAL; r += nwarps) {
        long rs = r;
        const float* src;
        float* dst;
        if (rs < ROWS_PER_STACK) { src = hs; dst = hs_out; }
        else { rs -= ROWS_PER_STACK; src = cs; dst = cs_out; }
        int s = (int)(rs >> 8);
        int b = (int)(rs & 255);
        if (s == pos[b] + 1) continue;
        const float4* s4 = (const float4*)(src + rs * 512);
        float4* d4 = (float4*)(dst + rs * 512);
        float4 v0 = __ldcs(s4 + lane);
        float4 v1 = __ldcs(s4 + lane + 32);
        float4 v2 = __ldcs(s4 + lane + 64);
        float4 v3 = __ldcs(s4 + lane + 96);
        __stcs(d4 + lane, v0);
        __stcs(d4 + lane + 32, v1);
        __stcs(d4 + lane + 64, v2);
        __stcs(d4 + lane + 96, v3);
    }
}

// ---------------- prologue: gather + weight split (gate-interleaved) + bias ----------------
#define WPREP_CTAS 128
union BF8U { __nv_bfloat16 b[8]; uint4 u; };

__global__ void __launch_bounds__(256) k_prologue(
        const float* __restrict__ x, const float* __restrict__ hs, const float* __restrict__ cs,
        const float* __restrict__ wih0, const float* __restrict__ whh0,
        const float* __restrict__ bih0, const float* __restrict__ bhh0,
        const float* __restrict__ wih1, const float* __restrict__ whh1,
        const float* __restrict__ bih1, const float* __restrict__ bhh1,
        const int* __restrict__ pos) {
    int bid = blockIdx.x;
    int t = threadIdx.x;
    if (bid < BB) {
        int b = bid, h = t;
        int s = pos[b];
        size_t idx = (((size_t)s * BB + b) * HH + h) * 2;
        float2 hv = *(const float2*)(hs + idx);
        float2 cv = *(const float2*)(cs + idx);
        __nv_bfloat16 hi, lo;
        bfsplit(x[b * INF + h], hi, lo);
        g_XH0hi[b * KTOT + h] = hi; g_XH0lo[b * KTOT + h] = lo;
        bfsplit(hv.x, hi, lo);
        g_XH0hi[b * KTOT + INF + h] = hi; g_XH0lo[b * KTOT + INF + h] = lo;
        bfsplit(hv.y, hi, lo);
        g_XH1hi[b * KTOT + INF + h] = hi; g_XH1lo[b * KTOT + INF + h] = lo;
        g_Cp0[b * HH + h] = cv.x;
        g_Cp1[b * HH + h] = cv.y;
        return;
    }
    if (bid < BB + WPREP_CTAS) {
        // weight split into bf16 hi/lo; layout [n'][k], n' = h*4+gate, k = [wih | whh]
        int tid0 = (bid - BB) * 256 + t;
        for (int g = tid0; g < 2 * NG * 64; g += WPREP_CTAS * 256) {
            int layer = g >> 16;
            int rem = g & 65535;
            int np = rem >> 6;               // n' 0..1023
            int k8 = (rem & 63) * 8;
            int hid = np >> 2, gate = np & 3;
            int orign = gate * HH + hid;
            const float* wih = layer ? wih1 : wih0;
            const float* whh = layer ? whh1 : whh0;
            const float* srcp = (k8 < INF) ? (wih + (size_t)orign * INF + k8)
                                           : (whh + (size_t)orign * INF + (k8 - INF));
            float4 a = *(const float4*)srcp;
            float4 bq = *(const float4*)(srcp + 4);
            float v[8] = {a.x, a.y, a.z, a.w, bq.x, bq.y, bq.z, bq.w};
            BF8U uhi, ulo;
#pragma unroll
            for (int j = 0; j < 8; j++) bfsplit(v[j], uhi.b[j], ulo.b[j]);
            __nv_bfloat16* dhi = layer ? g_W1hi : g_W0hi;
            __nv_bfloat16* dlo = layer ? g_W1lo : g_W0lo;
            *(uint4*)(dhi + (size_t)np * KTOT + k8) = uhi.u;
            *(uint4*)(dlo + (size_t)np * KTOT + k8) = ulo.u;
        }
        return;
    }
    // combined bias in n'-space
#pragma unroll
    for (int e = 0; e < 8; e++) {
        int idx = e * 256 + t;
        int layer = idx >> 10;
        int np = idx & 1023;
        int hid = np >> 2, gate = np & 3;
        int orign = gate * HH + hid;
        float v = (layer ? bih1 : bih0)[orign] + (layer ? bhh1 : bhh0)[orign];
        (layer ? g_Bias1 : g_Bias0)[np] = v;
    }
}

// ---------------- fused HMMA GEMM + LSTM epilogue ----------------
// gates'[256, 1024] = XH[256,512] @ W'[1024,512]^T  (n' gate-interleaved)
// 128 CTAs: tile 32(m) x 64(n'), 16 warps (512 thr), warp tile 16x8.
// K chunks of 128 (NCHUNK=4), double-buffered smem. 3-term bf16 split.
#define GEMM_CTAS 128
#define GEMM_THREADS 512
#define KC 128
#define APADK 136                        // bf16 row stride in smem (128 + 8 pad)
#define A_BYTES (32 * APADK * 2)         // 8704 per A array
#define B_BYTES (64 * APADK * 2)         // 17408 per B array
#define STAGE_BYTES (2 * A_BYTES + 2 * B_BYTES)   // 52224
#define SMEM_GEMM (2 * STAGE_BYTES)               // 104448
#define OFF_AH(p) ((p) * STAGE_BYTES)
#define OFF_AL(p) ((p) * STAGE_BYTES + A_BYTES)
#define OFF_BH(p) ((p) * STAGE_BYTES + 2 * A_BYTES)
#define OFF_BL(p) ((p) * STAGE_BYTES + 2 * A_BYTES + B_BYTES)
#define NCHUNK 4

template <int LAYER>
__global__ void __launch_bounds__(GEMM_THREADS) k_gemm(
        const float* __restrict__ hs, const float* __restrict__ cs,
        float* __restrict__ hs_out, float* __restrict__ cs_out,
        const int* __restrict__ op, const int* __restrict__ pos,
        float* __restrict__ out) {
    const int bid = blockIdx.x;
    const int t = threadIdx.x;

    extern __shared__ char smem[];
    const uint32_t sb = smem_u32(smem);

    const __nv_bfloat16* __restrict__ Ahi = LAYER ? g_XH1hi : g_XH0hi;
    const __nv_bfloat16* __restrict__ Alo = LAYER ? g_XH1lo : g_XH0lo;
    const __nv_bfloat16* __restrict__ Bhi = LAYER ? g_W1hi : g_W0hi;
    const __nv_bfloat16* __restrict__ Blo = LAYER ? g_W1lo : g_W0lo;

    const int m0 = (bid & 7) * 32;      // 8 m tiles
    const int n0 = (bid >> 3) * 64;     // 16 n' tiles
    const int wid = t >> 5, lane = t & 31;
    const int wm = (wid & 1) * 16;      // warp m offset (0/16)
    const int wn = (wid >> 1) * 8;      // warp n offset (0..56)
    const int lr = lane >> 2;           // 0..7
    const int lc = (lane & 3) * 2;      // 0,2,4,6

    // cp.async: 6 items/thread per chunk. rowi = t>>4 (0..31), ji = t&15.
    const int rowi = t >> 4, ji = t & 15;

    float acc[4];
    acc[0] = acc[1] = acc[2] = acc[3] = 0.f;

    auto load_chunk = [&](int c, int p) {
        int kc = c * KC;
        // e0: AH row rowi, e1: AL row rowi
        cp16(sb + OFF_AH(p) + rowi * (APADK * 2) + ji * 16,
             Ahi + (size_t)(m0 + rowi) * KTOT + kc + ji * 8);
        cp16(sb + OFF_AL(p) + rowi * (APADK * 2) + ji * 16,
             Alo + (size_t)(m0 + rowi) * KTOT + kc + ji * 8);
        // e2/e3: BH rows rowi, rowi+32
        cp16(sb + OFF_BH(p) + rowi * (APADK * 2) + ji * 16,
             Bhi + (size_t)(n0 + rowi) * KTOT + kc + ji * 8);
        cp16(sb + OFF_BH(p) + (rowi + 32) * (APADK * 2) + ji * 16,
             Bhi + (size_t)(n0 + rowi + 32) * KTOT + kc + ji * 8);
        // e4/e5: BL rows rowi, rowi+32
        cp16(sb + OFF_BL(p) + rowi * (APADK * 2) + ji * 16,
             Blo + (size_t)(n0 + rowi) * KTOT + kc + ji * 8);
        cp16(sb + OFF_BL(p) + (rowi + 32) * (APADK * 2) + ji * 16,
             Blo + (size_t)(n0 + rowi + 32) * KTOT + kc + ji * 8);
    };

    load_chunk(0, 0); CP_COMMIT();

#pragma unroll 1
    for (int c = 0; c < NCHUNK; c++) {
        int p = c & 1;
        if (c + 1 < NCHUNK) { load_chunk(c + 1, p ^ 1); CP_COMMIT(); CP_WAIT(1); }
        else                { CP_WAIT(0); }
        __syncthreads();

        const __nv_bfloat16* ah = (const __nv_bfloat16*)(smem + OFF_AH(p));
        const __nv_bfloat16* al = (const __nv_bfloat16*)(smem + OFF_AL(p));
        const __nv_bfloat16* bh = (const __nv_bfloat16*)(smem + OFF_BH(p));
        const __nv_bfloat16* bl = (const __nv_bfloat16*)(smem + OFF_BL(p));

#pragma unroll
        for (int k0 = 0; k0 < KC; k0 += 16) {
            const int r = wm + lr;
            const int n = wn + lr;
            const int cc = k0 + lc;
            uint32_t AH4[4], AL4[4], BH2[2], BL2[2];
            AH4[0] = *(const uint32_t*)(ah + r * APADK + cc);
            AH4[1] = *(const uint32_t*)(ah + (r + 8) * APADK + cc);
            AH4[2] = *(const uint32_t*)(ah + r * APADK + cc + 8);
            AH4[3] = *(const uint32_t*)(ah + (r + 8) * APADK + cc + 8);
            AL4[0] = *(const uint32_t*)(al + r * APADK + cc);
            AL4[1] = *(const uint32_t*)(al + (r + 8) * APADK + cc);
            AL4[2] = *(const uint32_t*)(al + r * APADK + cc + 8);
            AL4[3] = *(const uint32_t*)(al + (r + 8) * APADK + cc + 8);
            BH2[0] = *(const uint32_t*)(bh + n * APADK + cc);
            BH2[1] = *(const uint32_t*)(bh + n * APADK + cc + 8);
            BL2[0] = *(const uint32_t*)(bl + n * APADK + cc);
            BL2[1] = *(const uint32_t*)(bl + n * APADK + cc + 8);
            hmma(acc, AH4[0], AH4[1], AH4[2], AH4[3], BH2[0], BH2[1]);
            hmma(acc, AH4[0], AH4[1], AH4[2], AH4[3], BL2[0], BL2[1]);
            hmma(acc, AL4[0], AL4[1], AL4[2], AL4[3], BH2[0], BH2[1]);
        }
        __syncthreads();
    }

    // ---- fused LSTM epilogue ----
    float* Gs = (float*)smem;   // 32 x 68 fp32 gates (pre-bias), reuses stage smem
    {
        int r = wm + lr;
        int n = wn + lc;
        *(float2*)(Gs + r * 68 + n)       = make_float2(acc[0], acc[1]);
        *(float2*)(Gs + (r + 8) * 68 + n) = make_float2(acc[2], acc[3]);
    }
    __syncthreads();

    const float* __restrict__ Bias = LAYER ? g_Bias1 : g_Bias0;
    const float* __restrict__ Cp   = LAYER ? g_Cp1 : g_Cp0;
    {
        int mb = t >> 4, hh = t & 15;   // 32 x 16
        int b = m0 + mb, h = (n0 >> 2) + hh;
        float4 g4 = *(const float4*)(Gs + mb * 68 + hh * 4);
        float4 bi4 = *(const float4*)(Bias + n0 + hh * 4);
        float gi = g4.x + bi4.x, gf = g4.y + bi4.y, gg = g4.z + bi4.z, go = g4.w + bi4.w;
        float si = 1.0f / (1.0f + expf(-gi));
        float sf = 1.0f / (1.0f + expf(-gf));
        float so = 1.0f / (1.0f + expf(-go));
        float c2 = sf * Cp[b * HH + h] + si * tanhf(gg);
        float h2 = so * tanhf(c2);

        if (LAYER == 0) {
            g_H0[b * HH + h] = h2;
            g_C0[b * HH + h] = c2;
            __nv_bfloat16 hi_, lo_;
            bfsplit(h2, hi_, lo_);
            g_XH1hi[b * KTOT + h] = hi_;
            g_XH1lo[b * KTOT + h] = lo_;
        } else {
            int pp = pos[b];
            float h0 = g_H0[b * HH + h];
            float c0 = g_C0[b * HH + h];
            size_t base = (((size_t)(pp + 1) * BB + b) * HH + h) * 2;
            *(float2*)(hs_out + base) = make_float2(h0, h2);
            *(float2*)(cs_out + base) = make_float2(c0, c2);
            if (h == HH - 1) {
                int o = op[b];
                float2 hv, cv;
                if (o == 1) { hv = make_float2(h0, h2); cv = make_float2(c0, c2); }
                else {
                    size_t gi2 = (((size_t)(pp + o) * BB + b) * HH + (HH - 1)) * 2;
                    hv = *(const float2*)(hs + gi2);
                    cv = *(const float2*)(cs + gi2);
                }
                *(float2*)(out + b * 2) = hv;            // h_out (1,B,L)
                *(float2*)(out + BB * 2 + b * 2) = cv;   // c_out (1,B,L)
            }
        }
    }
}

// ---------------- launch ----------------
extern "C" void kernel_launch(void* const* d_in, const int* in_sizes, int n_in,
                              void* d_out, int out_size) {
    const float* x    = (const float*)d_in[0];
    const float* hs   = (const float*)d_in[1];
    const float* cs   = (const float*)d_in[2];
    const float* wih0 = (const float*)d_in[3];
    const float* whh0 = (const float*)d_in[4];
    const float* bih0 = (const float*)d_in[5];
    const float* bhh0 = (const float*)d_in[6];
    const float* wih1 = (const float*)d_in[7];
    const float* whh1 = (const float*)d_in[8];
    const float* bih1 = (const float*)d_in[9];
    const float* bhh1 = (const float*)d_in[10];
    const int*   op   = (const int*)d_in[11];
    const int*   pos  = (const int*)d_in[12];
    float* out = (float*)d_out;

    float* hs_out = out + 2 * BB * 2;
    float* cs_out = hs_out + STACKN;

    static cudaStream_t s2 = nullptr;
    static cudaEvent_t evFork = nullptr, evJoin = nullptr;
    if (!s2) {
        cudaStreamCreate(&s2);
        cudaEventCreateWithFlags(&evFork, cudaEventDisableTiming);
        cudaEventCreateWithFlags(&evJoin, cudaEventDisableTiming);
        cudaFuncSetAttribute(k_gemm<0>, cudaFuncAttributeMaxDynamicSharedMemorySize, SMEM_GEMM);
        cudaFuncSetAttribute(k_gemm<1>, cudaFuncAttributeMaxDynamicSharedMemorySize, SMEM_GEMM);
    }

    // fork: bulk copy starts immediately on s2
    cudaEventRecord(evFork, 0);
    cudaStreamWaitEvent(s2, evFork, 0);
    k_copy<<<COPY_CTAS, 256, 0, s2>>>(hs, cs, hs_out, cs_out, pos);
    cudaEventRecord(evJoin, s2);

    // compute chain on the main stream (concurrent with copy)
    k_prologue<<<BB + WPREP_CTAS + 1, 256>>>(
        x, hs, cs, wih0, whh0, bih0, bhh0, wih1, whh1, bih1, bhh1, pos);
    k_gemm<0><<<GEMM_CTAS, GEMM_THREADS, SMEM_GEMM>>>(hs, cs, hs_out, cs_out, op, pos, out);
    k_gemm<1><<<GEMM_CTAS, GEMM_THREADS, SMEM_GEMM>>>(hs, cs, hs_out, cs_out, op, pos, out);

    // join
    cudaStreamWaitEvent(0, evJoin, 0);
}